// round 7
// baseline (speedup 1.0000x reference)
#include <cuda_runtime.h>
#include <cstdint>

// Problem constants
#define BH      64      // B*H
#define SEQ     2048
#define HD      64
#define BM      128     // query rows per CTA
#define BK      128     // keys per tile
#define NT      (SEQ/BK)  // 16 key tiles
#define KS      68      // K smem row stride (floats) — ldsm-clean
#define VS      72      // V smem row stride (floats) — conflict-free scalar B loads
#define PS      132     // P smem row stride (floats) — ldsm-clean
#define NTHREADS 512

#define KVELEMS ((size_t)BH * SEQ * HD)   // 8,388,608 floats per tensor

// smem layout (float offsets)
#define OFF_K0  0
#define OFF_K1  (BK*KS)
#define OFF_V0  (2*BK*KS)
#define OFF_V1  (2*BK*KS + BK*VS)
#define OFF_PS  (2*BK*KS + 2*BK*VS)
#define SMEM_FLOATS (OFF_PS + BM*PS)
#define SMEM_BYTES  (SMEM_FLOATS * 4)   // 210944

// tf32-pre-rounded copies of K and V (32 MB each) — static scratch, no allocs
__device__ float g_Kr[KVELEMS];
__device__ float g_Vr[KVELEMS];

__device__ __forceinline__ uint32_t f2tf32(float x) {
    uint32_t r;
    asm("cvt.rna.tf32.f32 %0, %1;" : "=r"(r) : "f"(x));
    return r;
}

__device__ __forceinline__ float ex2(float x) {
    float y;
    asm("ex2.approx.f32 %0, %1;" : "=f"(y) : "f"(x));
    return y;
}

__device__ __forceinline__ void ldsm4(uint32_t* r, uint32_t addr) {
    asm volatile("ldmatrix.sync.aligned.m8n8.x4.shared.b16 {%0,%1,%2,%3}, [%4];"
        : "=r"(r[0]), "=r"(r[1]), "=r"(r[2]), "=r"(r[3]) : "r"(addr));
}

__device__ __forceinline__ void mma_tf32(float* c, const uint32_t* a, uint32_t b0, uint32_t b1) {
    asm volatile(
        "mma.sync.aligned.m16n8k8.row.col.f32.tf32.tf32.f32 "
        "{%0,%1,%2,%3}, {%4,%5,%6,%7}, {%8,%9}, {%0,%1,%2,%3};"
        : "+f"(c[0]), "+f"(c[1]), "+f"(c[2]), "+f"(c[3])
        : "r"(a[0]), "r"(a[1]), "r"(a[2]), "r"(a[3]), "r"(b0), "r"(b1));
}

__device__ __forceinline__ void cpa16(uint32_t dst, const void* src) {
    asm volatile("cp.async.ca.shared.global [%0], [%1], 16;" :: "r"(dst), "l"(src) : "memory");
}
__device__ __forceinline__ void cpa_commit() { asm volatile("cp.async.commit_group;" ::: "memory"); }
__device__ __forceinline__ void cpa_wait0()  { asm volatile("cp.async.wait_group 0;" ::: "memory"); }

__device__ __forceinline__ void copy_tile(uint32_t smem_base_bytes, int off_floats, int stride,
                                          const float* src, int tid) {
    uint32_t dst0 = smem_base_bytes + (uint32_t)off_floats * 4;
    #pragma unroll
    for (int j = 0; j < 4; j++) {
        int c  = tid + j * NTHREADS;
        int r  = c >> 4;
        int c4 = (c & 15) * 4;
        cpa16(dst0 + (uint32_t)(r * stride + c4) * 4, src + r * HD + c4);
    }
}

// ---- prep: round K,V to tf32 once ----
__global__ __launch_bounds__(256)
void prep_kernel(const float* __restrict__ k, const float* __restrict__ v)
{
    size_t i = (size_t)blockIdx.x * blockDim.x + threadIdx.x;   // float4 index
    if (i >= KVELEMS / 4) return;
    float4 a = ((const float4*)k)[i];
    float4 b = ((const float4*)v)[i];
    a.x = __uint_as_float(f2tf32(a.x)); a.y = __uint_as_float(f2tf32(a.y));
    a.z = __uint_as_float(f2tf32(a.z)); a.w = __uint_as_float(f2tf32(a.w));
    b.x = __uint_as_float(f2tf32(b.x)); b.y = __uint_as_float(f2tf32(b.y));
    b.z = __uint_as_float(f2tf32(b.z)); b.w = __uint_as_float(f2tf32(b.w));
    ((float4*)g_Kr)[i] = a;
    ((float4*)g_Vr)[i] = b;
}

__global__ __launch_bounds__(NTHREADS, 1)
void attn_kernel(const float* __restrict__ q, float* __restrict__ out,
                 float* __restrict__ attn)
{
    extern __shared__ float smem[];
    const uint32_t sb = (uint32_t)__cvta_generic_to_shared(smem);

    const int tid  = threadIdx.x;
    const int w    = tid >> 5;
    const int lane = tid & 31;
    const int g    = lane >> 2;
    const int t    = lane & 3;
    const int wm   = w & 3;
    const int wn   = w >> 2;
    const int bh   = blockIdx.y;
    const int qt   = blockIdx.x;

    const size_t qoff = ((size_t)bh * SEQ + (size_t)qt * BM) * HD;
    const float* qp = q + qoff;
    const float* kp = g_Kr + (size_t)bh * SEQ * HD;
    const float* vp = g_Vr + (size_t)bh * SEQ * HD;

    const int a_row = wm * 32 + (lane & 7) + 8 * ((lane >> 3) & 1);
    const int a_col = (lane >> 4) * 4;
    const uint32_t qaddr = sb + (uint32_t)(OFF_K0 + a_row * KS + a_col) * 4;
    const uint32_t paddr = sb + (uint32_t)(OFF_PS + a_row * PS + a_col) * 4;
    const uint32_t boff  = (uint32_t)((wn * 32 + (lane & 7)) * KS + (lane >> 3) * 4) * 4;

    const float QSCALE = 0.125f * 1.44269504088896f;   // (1/temp) * log2(e)

    // ---- Stage Q (scaled, tf32-rounded) into K0, keep A-fragments resident ----
    #pragma unroll
    for (int i = tid; i < BM * (HD / 4); i += NTHREADS) {
        int r = i >> 4, c = (i & 15) * 4;
        float4 val = *(const float4*)(qp + r * HD + c);
        float* dst = smem + OFF_K0 + r * KS + c;
        dst[0] = __uint_as_float(f2tf32(val.x * QSCALE));
        dst[1] = __uint_as_float(f2tf32(val.y * QSCALE));
        dst[2] = __uint_as_float(f2tf32(val.z * QSCALE));
        dst[3] = __uint_as_float(f2tf32(val.w * QSCALE));
    }
    __syncthreads();

    uint32_t qa[2][8][4];
    #pragma unroll
    for (int mb = 0; mb < 2; mb++)
        #pragma unroll
        for (int ks = 0; ks < 8; ks++)
            ldsm4(qa[mb][ks], qaddr + (uint32_t)(mb * 16 * KS * 4) + ks * 32);
    __syncthreads();

    // ---- Phase A: partial row sums of 2^(scores) ----
    copy_tile(sb, OFF_K0, KS, kp, tid);
    cpa_commit();

    float rs[2][2] = {{0.f, 0.f}, {0.f, 0.f}};
    #pragma unroll 1
    for (int kt = 0; kt < NT; kt++) {
        cpa_wait0();
        __syncthreads();
        if (kt + 1 < NT) {
            copy_tile(sb, (kt & 1) ? OFF_K0 : OFF_K1, KS, kp + (size_t)(kt + 1) * BK * HD, tid);
            cpa_commit();
        }
        uint32_t bb = sb + (uint32_t)((kt & 1) ? OFF_K1 : OFF_K0) * 4 + boff;
        #pragma unroll
        for (int nb = 0; nb < 4; nb++) {
            float sa0[4] = {0.f,0.f,0.f,0.f};
            float sa1[4] = {0.f,0.f,0.f,0.f};
            #pragma unroll
            for (int ksq = 0; ksq < 4; ksq++) {
                uint32_t b[4];
                ldsm4(b, bb + ksq * 64);
                mma_tf32(sa0, qa[0][2*ksq],   b[0], b[1]);
                mma_tf32(sa0, qa[0][2*ksq+1], b[2], b[3]);
                mma_tf32(sa1, qa[1][2*ksq],   b[0], b[1]);
                mma_tf32(sa1, qa[1][2*ksq+1], b[2], b[3]);
            }
            rs[0][0] += ex2(sa0[0]) + ex2(sa0[1]);
            rs[0][1] += ex2(sa0[2]) + ex2(sa0[3]);
            rs[1][0] += ex2(sa1[0]) + ex2(sa1[1]);
            rs[1][1] += ex2(sa1[2]) + ex2(sa1[3]);
            bb += 8 * KS * 4;
        }
        __syncthreads();
    }

    // cross-warp rowsum combine via Ps scratch (4 n-warps)
    float* rsum = smem + OFF_PS;   // [4][128]
    #pragma unroll
    for (int mb = 0; mb < 2; mb++)
        #pragma unroll
        for (int rg = 0; rg < 2; rg++) {
            float vsum = rs[mb][rg];
            vsum += __shfl_xor_sync(0xffffffffu, vsum, 1);
            vsum += __shfl_xor_sync(0xffffffffu, vsum, 2);
            if (t == 0) rsum[wn * 128 + wm * 32 + mb * 16 + rg * 8 + g] = vsum;
        }
    __syncthreads();
    float inv[2][2];
    #pragma unroll
    for (int mb = 0; mb < 2; mb++)
        #pragma unroll
        for (int rg = 0; rg < 2; rg++) {
            int r = wm * 32 + mb * 16 + rg * 8 + g;
            inv[mb][rg] = 1.0f / (rsum[r] + rsum[128 + r] + rsum[256 + r] + rsum[384 + r]);
        }
    __syncthreads();

    // ---- Phase B ----
    float oc[2][2][4];
    #pragma unroll
    for (int mb = 0; mb < 2; mb++)
        #pragma unroll
        for (int nb = 0; nb < 2; nb++)
            { oc[mb][nb][0]=0.f; oc[mb][nb][1]=0.f; oc[mb][nb][2]=0.f; oc[mb][nb][3]=0.f; }

    float* attn_base = attn + ((size_t)bh * SEQ + (size_t)qt * BM) * SEQ;

    copy_tile(sb, OFF_K0, KS, kp, tid);
    copy_tile(sb, OFF_V0, VS, vp, tid);
    cpa_commit();

    #pragma unroll 1
    for (int kt = 0; kt < NT; kt++) {
        cpa_wait0();
        __syncthreads();
        if (kt + 1 < NT) {
            copy_tile(sb, (kt & 1) ? OFF_K0 : OFF_K1, KS, kp + (size_t)(kt + 1) * BK * HD, tid);
            copy_tile(sb, (kt & 1) ? OFF_V0 : OFF_V1, VS, vp + (size_t)(kt + 1) * BK * HD, tid);
            cpa_commit();
        }
        uint32_t bb = sb + (uint32_t)((kt & 1) ? OFF_K1 : OFF_K0) * 4 + boff;
        const float* Vs = smem + ((kt & 1) ? OFF_V1 : OFF_V0);
        float* ap = attn_base + kt * BK;

        #pragma unroll
        for (int nb = 0; nb < 4; nb++) {
            float sa0[4] = {0.f,0.f,0.f,0.f};
            float sa1[4] = {0.f,0.f,0.f,0.f};
            #pragma unroll
            for (int ksq = 0; ksq < 4; ksq++) {
                uint32_t b[4];
                ldsm4(b, bb + ksq * 64);
                mma_tf32(sa0, qa[0][2*ksq],   b[0], b[1]);
                mma_tf32(sa0, qa[0][2*ksq+1], b[2], b[3]);
                mma_tf32(sa1, qa[1][2*ksq],   b[0], b[1]);
                mma_tf32(sa1, qa[1][2*ksq+1], b[2], b[3]);
            }
            const int col = wn * 32 + nb * 8 + 2 * t;
            const int r00 = wm * 32 + g;
            float* PsW = smem + OFF_PS;
            {
                float p0 = ex2(sa0[0]) * inv[0][0];
                float p1 = ex2(sa0[1]) * inv[0][0];
                float p2 = ex2(sa0[2]) * inv[0][1];
                float p3 = ex2(sa0[3]) * inv[0][1];
                // smem copy pre-rounded to tf32 (feeds PV MMA); gmem keeps full fp32
                *(float2*)&PsW[ r00      * PS + col] =
                    make_float2(__uint_as_float(f2tf32(p0)), __uint_as_float(f2tf32(p1)));
                *(float2*)&PsW[(r00 + 8) * PS + col] =
                    make_float2(__uint_as_float(f2tf32(p2)), __uint_as_float(f2tf32(p3)));
                *(float2*)(ap + (size_t) r00      * SEQ + col) = make_float2(p0, p1);
                *(float2*)(ap + (size_t)(r00 + 8) * SEQ + col) = make_float2(p2, p3);
            }
            {
                float p0 = ex2(sa1[0]) * inv[1][0];
                float p1 = ex2(sa1[1]) * inv[1][0];
                float p2 = ex2(sa1[2]) * inv[1][1];
                float p3 = ex2(sa1[3]) * inv[1][1];
                *(float2*)&PsW[(r00 + 16) * PS + col] =
                    make_float2(__uint_as_float(f2tf32(p0)), __uint_as_float(f2tf32(p1)));
                *(float2*)&PsW[(r00 + 24) * PS + col] =
                    make_float2(__uint_as_float(f2tf32(p2)), __uint_as_float(f2tf32(p3)));
                *(float2*)(ap + (size_t)(r00 + 16) * SEQ + col) = make_float2(p0, p1);
                *(float2*)(ap + (size_t)(r00 + 24) * SEQ + col) = make_float2(p2, p3);
            }
            bb += 8 * KS * 4;
        }
        __syncthreads();   // Ps complete, K consumed

        // O += P @ V   (all operands pre-rounded: no cvt in the chain)
        const int vcol = wn * 16 + g;
        #pragma unroll
        for (int kb = 0; kb < 16; kb++) {
            uint32_t pa[2][4];
            #pragma unroll
            for (int mb = 0; mb < 2; mb++)
                ldsm4(pa[mb], paddr + (uint32_t)(mb * 16 * PS * 4) + kb * 32);
            #pragma unroll
            for (int nb = 0; nb < 2; nb++) {
                uint32_t b0 = __float_as_uint(Vs[(kb * 8 + t    ) * VS + vcol + nb * 8]);
                uint32_t b1 = __float_as_uint(Vs[(kb * 8 + t + 4) * VS + vcol + nb * 8]);
                mma_tf32(oc[0][nb], pa[0], b0, b1);
                mma_tf32(oc[1][nb], pa[1], b0, b1);
            }
        }
    }

    // ---- write O ----
    float* op = out + qoff;
    #pragma unroll
    for (int mb = 0; mb < 2; mb++) {
        const int r00 = wm * 32 + mb * 16 + g;
        #pragma unroll
        for (int nb = 0; nb < 2; nb++) {
            const int col = wn * 16 + nb * 8 + 2 * t;
            *(float2*)(op + r00       * HD + col) = make_float2(oc[mb][nb][0], oc[mb][nb][1]);
            *(float2*)(op + (r00 + 8) * HD + col) = make_float2(oc[mb][nb][2], oc[mb][nb][3]);
        }
    }
}

extern "C" void kernel_launch(void* const* d_in, const int* in_sizes, int n_in,
                              void* d_out, int out_size)
{
    const float* q = (const float*)d_in[0];
    const float* k = (const float*)d_in[1];
    const float* v = (const float*)d_in[2];
    float* out  = (float*)d_out;
    float* attn = out + (size_t)BH * SEQ * HD;   // output first, then attn

    cudaFuncSetAttribute(attn_kernel, cudaFuncAttributeMaxDynamicSharedMemorySize, SMEM_BYTES);

    // 1) round K,V to tf32 once
    prep_kernel<<<(unsigned)((KVELEMS / 4 + 255) / 256), 256>>>(k, v);

    // 2) attention
    dim3 grid(SEQ / BM, BH);
    attn_kernel<<<grid, NTHREADS, SMEM_BYTES>>>(q, out, attn);
}

// round 8
// speedup vs baseline: 2.5371x; 2.5371x over previous
#include <cuda_runtime.h>
#include <cuda_fp16.h>
#include <cstdint>

// Problem constants
#define BH      64
#define SEQ     2048
#define HD      64
#define BM      128
#define BK      128
#define NT      (SEQ/BK)
#define KSH     72      // K/V smem row stride (halfs) = 144B : ldsm-clean per 8-row phase
#define PSH     136     // P smem row stride (halfs) = 272B : ldsm-clean per 8-row phase
#define NTHREADS 512

#define KVELEMS ((size_t)BH * SEQ * HD)

// smem layout (half offsets)
#define OFF_K0  0
#define OFF_K1  (BK*KSH)            // 9216
#define OFF_V0  (2*BK*KSH)          // 18432
#define OFF_V1  (3*BK*KSH)          // 27648
#define OFF_PS  (4*BK*KSH)          // 36864
#define SMEM_HALFS (OFF_PS + BM*PSH)  // 54272
#define SMEM_BYTES (SMEM_HALFS * 2)   // 108544

// fp16 copies of K and V (16 MB each) — static scratch, no allocs
__device__ __half g_Kh[KVELEMS];
__device__ __half g_Vh[KVELEMS];

__device__ __forceinline__ float ex2(float x) {
    float y;
    asm("ex2.approx.f32 %0, %1;" : "=f"(y) : "f"(x));
    return y;
}

__device__ __forceinline__ uint32_t h2u(__half2 h) { return *(uint32_t*)&h; }

__device__ __forceinline__ void ldsm4(uint32_t* r, uint32_t addr) {
    asm volatile("ldmatrix.sync.aligned.m8n8.x4.shared.b16 {%0,%1,%2,%3}, [%4];"
        : "=r"(r[0]), "=r"(r[1]), "=r"(r[2]), "=r"(r[3]) : "r"(addr));
}
__device__ __forceinline__ void ldsm4t(uint32_t* r, uint32_t addr) {
    asm volatile("ldmatrix.sync.aligned.m8n8.x4.trans.shared.b16 {%0,%1,%2,%3}, [%4];"
        : "=r"(r[0]), "=r"(r[1]), "=r"(r[2]), "=r"(r[3]) : "r"(addr));
}

__device__ __forceinline__ void mma16816(float* c, const uint32_t* a, uint32_t b0, uint32_t b1) {
    asm volatile(
        "mma.sync.aligned.m16n8k16.row.col.f32.f16.f16.f32 "
        "{%0,%1,%2,%3}, {%4,%5,%6,%7}, {%8,%9}, {%0,%1,%2,%3};"
        : "+f"(c[0]), "+f"(c[1]), "+f"(c[2]), "+f"(c[3])
        : "r"(a[0]), "r"(a[1]), "r"(a[2]), "r"(a[3]), "r"(b0), "r"(b1));
}

__device__ __forceinline__ void cpa16(uint32_t dst, const void* src) {
    asm volatile("cp.async.ca.shared.global [%0], [%1], 16;" :: "r"(dst), "l"(src) : "memory");
}
__device__ __forceinline__ void cpa_commit() { asm volatile("cp.async.commit_group;" ::: "memory"); }
__device__ __forceinline__ void cpa_wait0()  { asm volatile("cp.async.wait_group 0;" ::: "memory"); }

// copy one 128x64 fp16 tile into smem (row stride KSH halfs)
__device__ __forceinline__ void copy_tile(uint32_t sb, int off_halfs, const __half* src, int tid) {
    uint32_t dst0 = sb + (uint32_t)off_halfs * 2;
    #pragma unroll
    for (int j = 0; j < 2; j++) {
        int c   = tid + j * NTHREADS;   // 0..1023 16B-chunks, 8 per row
        int r   = c >> 3;
        int c16 = (c & 7) * 8;          // half offset
        cpa16(dst0 + (uint32_t)(r * KSH + c16) * 2, src + r * HD + c16);
    }
}

// ---- prep: convert K,V to fp16 once ----
__global__ __launch_bounds__(256)
void prep_kernel(const float* __restrict__ k, const float* __restrict__ v)
{
    size_t i = (size_t)blockIdx.x * blockDim.x + threadIdx.x;   // 8-float chunk
    if (i >= KVELEMS / 8) return;
    const float4* k4 = (const float4*)k;
    const float4* v4 = (const float4*)v;
    float4 a0 = k4[2*i], a1 = k4[2*i+1];
    float4 b0 = v4[2*i], b1 = v4[2*i+1];
    uint4 kk, vv;
    kk.x = h2u(__floats2half2_rn(a0.x, a0.y)); kk.y = h2u(__floats2half2_rn(a0.z, a0.w));
    kk.z = h2u(__floats2half2_rn(a1.x, a1.y)); kk.w = h2u(__floats2half2_rn(a1.z, a1.w));
    vv.x = h2u(__floats2half2_rn(b0.x, b0.y)); vv.y = h2u(__floats2half2_rn(b0.z, b0.w));
    vv.z = h2u(__floats2half2_rn(b1.x, b1.y)); vv.w = h2u(__floats2half2_rn(b1.z, b1.w));
    ((uint4*)g_Kh)[i] = kk;
    ((uint4*)g_Vh)[i] = vv;
}

__global__ __launch_bounds__(NTHREADS, 1)
void attn_kernel(const float* __restrict__ q, float* __restrict__ out,
                 float* __restrict__ attn)
{
    extern __shared__ __half smemh[];
    const uint32_t sb = (uint32_t)__cvta_generic_to_shared(smemh);

    const int tid  = threadIdx.x;
    const int lane = tid & 31;
    const int w    = tid >> 5;
    const int g    = lane >> 2;
    const int t    = lane & 3;
    const int wm   = w & 3;     // rows wm*32..+31
    const int wn   = w >> 2;    // S-cols wn*32..+31 ; O-cols wn*16..+15
    const int bh   = blockIdx.y;
    const int qt   = blockIdx.x;

    const size_t qoff = ((size_t)bh * SEQ + (size_t)qt * BM) * HD;
    const float* qp  = q + qoff;
    const __half* kp = g_Kh + (size_t)bh * SEQ * HD;
    const __half* vp = g_Vh + (size_t)bh * SEQ * HD;

    // ldmatrix lane addresses (byte offsets relative to region bases)
    const int a_row = (lane & 7) + 8 * ((lane >> 3) & 1);         // A frags (Q, P)
    const uint32_t qrel = (uint32_t)((wm * 32 + a_row) * KSH) * 2 + (lane >> 4) * 16;
    const uint32_t prel = (uint32_t)((wm * 32 + a_row) * PSH) * 2 + (lane >> 4) * 16;
    const int b_row = (lane & 7) + 8 * ((lane >> 4) & 1);         // QK B frags (K rows = n)
    const uint32_t brel = (uint32_t)((wn * 32 + b_row) * KSH) * 2 + ((lane >> 3) & 1) * 16;
    const int v_row = (lane & 7) + 8 * ((lane >> 3) & 1);         // PV B frags (V rows = k, trans)
    const uint32_t vrel = (uint32_t)(v_row * KSH) * 2 + wn * 32 + (lane >> 4) * 16;

    const float QSCALE = 0.125f * 1.44269504088896f;   // (1/temp) * log2(e)

    // ---- Stage Q (scaled -> fp16) into K0 region, keep A-fragments resident ----
    #pragma unroll
    for (int i = tid; i < BM * (HD / 4); i += NTHREADS) {
        int r = i >> 4, c = (i & 15) * 4;
        float4 val = *(const float4*)(qp + r * HD + c);
        uint2 pk = make_uint2(h2u(__floats2half2_rn(val.x * QSCALE, val.y * QSCALE)),
                              h2u(__floats2half2_rn(val.z * QSCALE, val.w * QSCALE)));
        *(uint2*)&smemh[OFF_K0 + r * KSH + c] = pk;
    }
    __syncthreads();

    uint32_t qa[2][4][4];    // [mb][k16-step][frag]
    #pragma unroll
    for (int mb = 0; mb < 2; mb++)
        #pragma unroll
        for (int ks = 0; ks < 4; ks++)
            ldsm4(qa[mb][ks], sb + qrel + (uint32_t)(mb * 16 * KSH * 2) + ks * 32);
    __syncthreads();

    // ---- Phase A: partial row sums of 2^(scores) ----
    copy_tile(sb, OFF_K0, kp, tid);
    cpa_commit();

    float rs[2][2] = {{0.f, 0.f}, {0.f, 0.f}};
    #pragma unroll 1
    for (int kt = 0; kt < NT; kt++) {
        cpa_wait0();
        __syncthreads();
        if (kt + 1 < NT) {
            copy_tile(sb, (kt & 1) ? OFF_K0 : OFF_K1, kp + (size_t)(kt + 1) * BK * HD, tid);
            cpa_commit();
        }
        uint32_t bK = sb + (uint32_t)((kt & 1) ? OFF_K1 : OFF_K0) * 2 + brel;
        #pragma unroll
        for (int nbq = 0; nbq < 2; nbq++) {
            float sa[2][2][4] = {};
            #pragma unroll
            for (int ks = 0; ks < 4; ks++) {
                uint32_t b[4];
                ldsm4(b, bK + (uint32_t)(nbq * 16 * KSH * 2) + ks * 32);
                mma16816(sa[0][0], qa[0][ks], b[0], b[1]);
                mma16816(sa[0][1], qa[0][ks], b[2], b[3]);
                mma16816(sa[1][0], qa[1][ks], b[0], b[1]);
                mma16816(sa[1][1], qa[1][ks], b[2], b[3]);
            }
            #pragma unroll
            for (int mb = 0; mb < 2; mb++)
                #pragma unroll
                for (int nb = 0; nb < 2; nb++) {
                    rs[mb][0] += ex2(sa[mb][nb][0]) + ex2(sa[mb][nb][1]);
                    rs[mb][1] += ex2(sa[mb][nb][2]) + ex2(sa[mb][nb][3]);
                }
        }
        __syncthreads();
    }

    // cross-warp rowsum combine (4 n-warps) via smem scratch in Ps region
    float* rsum = (float*)(smemh + OFF_PS);   // [4][128] floats
    #pragma unroll
    for (int mb = 0; mb < 2; mb++)
        #pragma unroll
        for (int rg = 0; rg < 2; rg++) {
            float vsum = rs[mb][rg];
            vsum += __shfl_xor_sync(0xffffffffu, vsum, 1);
            vsum += __shfl_xor_sync(0xffffffffu, vsum, 2);
            if (t == 0) rsum[wn * 128 + wm * 32 + mb * 16 + rg * 8 + g] = vsum;
        }
    __syncthreads();
    float inv[2][2];
    #pragma unroll
    for (int mb = 0; mb < 2; mb++)
        #pragma unroll
        for (int rg = 0; rg < 2; rg++) {
            int r = wm * 32 + mb * 16 + rg * 8 + g;
            inv[mb][rg] = 1.0f / (rsum[r] + rsum[128 + r] + rsum[256 + r] + rsum[384 + r]);
        }
    __syncthreads();

    // ---- Phase B ----
    float oc[2][2][4] = {};

    float* attn_base = attn + ((size_t)bh * SEQ + (size_t)qt * BM) * SEQ;

    copy_tile(sb, OFF_K0, kp, tid);
    copy_tile(sb, OFF_V0, vp, tid);
    cpa_commit();

    #pragma unroll 1
    for (int kt = 0; kt < NT; kt++) {
        cpa_wait0();
        __syncthreads();
        if (kt + 1 < NT) {
            copy_tile(sb, (kt & 1) ? OFF_K0 : OFF_K1, kp + (size_t)(kt + 1) * BK * HD, tid);
            copy_tile(sb, (kt & 1) ? OFF_V0 : OFF_V1, vp + (size_t)(kt + 1) * BK * HD, tid);
            cpa_commit();
        }
        uint32_t bK = sb + (uint32_t)((kt & 1) ? OFF_K1 : OFF_K0) * 2 + brel;
        uint32_t bV = sb + (uint32_t)((kt & 1) ? OFF_V1 : OFF_V0) * 2 + vrel;
        float* ap = attn_base + kt * BK;

        #pragma unroll
        for (int nbq = 0; nbq < 2; nbq++) {
            float sa[2][2][4] = {};
            #pragma unroll
            for (int ks = 0; ks < 4; ks++) {
                uint32_t b[4];
                ldsm4(b, bK + (uint32_t)(nbq * 16 * KSH * 2) + ks * 32);
                mma16816(sa[0][0], qa[0][ks], b[0], b[1]);
                mma16816(sa[0][1], qa[0][ks], b[2], b[3]);
                mma16816(sa[1][0], qa[1][ks], b[0], b[1]);
                mma16816(sa[1][1], qa[1][ks], b[2], b[3]);
            }
            #pragma unroll
            for (int mb = 0; mb < 2; mb++)
                #pragma unroll
                for (int nb = 0; nb < 2; nb++) {
                    const int col = wn * 32 + nbq * 16 + nb * 8 + 2 * t;
                    const int row = wm * 32 + mb * 16 + g;
                    float p0 = ex2(sa[mb][nb][0]) * inv[mb][0];
                    float p1 = ex2(sa[mb][nb][1]) * inv[mb][0];
                    float p2 = ex2(sa[mb][nb][2]) * inv[mb][1];
                    float p3 = ex2(sa[mb][nb][3]) * inv[mb][1];
                    *(uint32_t*)&smemh[OFF_PS + row * PSH + col]       = h2u(__floats2half2_rn(p0, p1));
                    *(uint32_t*)&smemh[OFF_PS + (row + 8) * PSH + col] = h2u(__floats2half2_rn(p2, p3));
                    *(float2*)(ap + (size_t)row       * SEQ + col) = make_float2(p0, p1);
                    *(float2*)(ap + (size_t)(row + 8) * SEQ + col) = make_float2(p2, p3);
                }
        }
        __syncthreads();   // Ps complete, K consumed

        // O += P @ V  (P A-frags via ldsm, V B-frags via ldsm.trans)
        #pragma unroll
        for (int kb = 0; kb < 8; kb++) {
            uint32_t pa0[4], pa1[4], vb[4];
            ldsm4 (pa0, sb + (uint32_t)OFF_PS * 2 + prel + kb * 32);
            ldsm4 (pa1, sb + (uint32_t)OFF_PS * 2 + prel + (uint32_t)(16 * PSH * 2) + kb * 32);
            ldsm4t(vb,  bV + (uint32_t)(kb * 16 * KSH * 2));
            mma16816(oc[0][0], pa0, vb[0], vb[1]);
            mma16816(oc[0][1], pa0, vb[2], vb[3]);
            mma16816(oc[1][0], pa1, vb[0], vb[1]);
            mma16816(oc[1][1], pa1, vb[2], vb[3]);
        }
        // next loop-top barrier protects Ps/V from overwrite
    }

    // ---- write O ----
    float* op = out + qoff;
    #pragma unroll
    for (int mb = 0; mb < 2; mb++) {
        const int r00 = wm * 32 + mb * 16 + g;
        #pragma unroll
        for (int nb = 0; nb < 2; nb++) {
            const int col = wn * 16 + nb * 8 + 2 * t;
            *(float2*)(op + r00       * HD + col) = make_float2(oc[mb][nb][0], oc[mb][nb][1]);
            *(float2*)(op + (r00 + 8) * HD + col) = make_float2(oc[mb][nb][2], oc[mb][nb][3]);
        }
    }
}

extern "C" void kernel_launch(void* const* d_in, const int* in_sizes, int n_in,
                              void* d_out, int out_size)
{
    const float* q = (const float*)d_in[0];
    const float* k = (const float*)d_in[1];
    const float* v = (const float*)d_in[2];
    float* out  = (float*)d_out;
    float* attn = out + (size_t)BH * SEQ * HD;   // output first, then attn

    cudaFuncSetAttribute(attn_kernel, cudaFuncAttributeMaxDynamicSharedMemorySize, SMEM_BYTES);

    prep_kernel<<<(unsigned)((KVELEMS / 8 + 255) / 256), 256>>>(k, v);

    dim3 grid(SEQ / BM, BH);
    attn_kernel<<<grid, NTHREADS, SMEM_BYTES>>>(q, out, attn);
}